// round 13
// baseline (speedup 1.0000x reference)
#include <cuda_runtime.h>
#include <cstdint>

#define NB 64
#define TT 100
#define NN 25
#define VV 128
#define CC 128
#define EE 64
#define NG (NB*TT)
#define GPT 5                 // graphs per tile
#define MR (GPT*NN)           // 125 rows per tile
#define NTILES (NG/GPT)       // 1280
#define XSTR 129              // X-tile stride: conflict-free scalar broadcasts
#define VSTR 132              // V-tile stride: 16B-aligned rows for LDS.128
#define WS_F (VV*CC)          // 16384
#define XV_F 16512            // max(128*129, 125*132); 16B-aligned buffer size
#define A2_F 640              // 625 padded -> downstream float4 alignment
#define CNT ((float)(NB*NN*CC))

__device__ float g_A2[NN*NN];
__device__ float g_rA[NN];
__device__ float g_b1w2[CC];
__device__ float g_W12[VV*CC];
__device__ float g_stats[2*TT];

typedef unsigned long long u64;

__device__ __forceinline__ u64 pk2(float v){
    u64 r; unsigned u = __float_as_uint(v);
    asm("mov.b64 %0, {%1, %1};" : "=l"(r) : "r"(u));
    return r;
}
__device__ __forceinline__ void ffma2(u64 &d, u64 a, u64 b){
    asm("fma.rn.f32x2 %0, %1, %2, %0;" : "+l"(d) : "l"(a), "l"(b));
}
__device__ __forceinline__ void upk(u64 v, float &lo, float &hi){
    unsigned a,b; asm("mov.b64 {%0, %1}, %2;" : "=r"(a), "=r"(b) : "l"(v));
    lo = __uint_as_float(a); hi = __uint_as_float(b);
}

// ---------------------------------------------------------------------------
// Parallel prep (256 thr): every block computes one W12 row; block 0 builds
// normalized adjacency via shared atomics, A2, rowsum, b1^T W2, and zeroes
// ALL stats (replay idempotence).  Edge dtype auto-detected.
// ---------------------------------------------------------------------------
__global__ void prep_k(const int* __restrict__ ei,
                       const float* __restrict__ W1,
                       const float* __restrict__ W2,
                       const float* __restrict__ b1){
    __shared__ float A[NN*NN];
    __shared__ float row[CC];
    __shared__ float deg[NN];
    __shared__ int   es[EE], et[EE];
    __shared__ int   flag;
    const int tid = threadIdx.x;
    const int bi  = blockIdx.x;

    if (tid < CC) row[tid] = W1[bi*CC + tid];
    __syncthreads();
    if (tid < CC){
        float s = 0.0f;
        #pragma unroll 8
        for (int j = 0; j < CC; j++) s += row[j]*W2[j*CC+tid];
        g_W12[bi*CC+tid] = s;
    }

    if (bi != 0) return;

    if (tid < 2*TT) g_stats[tid] = 0.0f;
    if (tid == 0)   flag = 1;
    if (tid < NN)   deg[tid] = 1.0f;            // self-loops
    for (int i = tid; i < NN*NN; i += blockDim.x) A[i] = 0.0f;
    __syncthreads();

    if (tid < EE){  // int64 layout = [v,0] pairs in first 128 words
        int a = ei[2*tid], b = ei[2*tid+1];
        if (b != 0 || (unsigned)a >= (unsigned)NN) atomicExch(&flag, 0);
    }
    __syncthreads();
    const bool is64 = (flag != 0);
    if (tid < EE){
        es[tid] = is64 ? ei[2*tid]        : ei[tid];
        et[tid] = is64 ? ei[2*(EE+tid)]   : ei[EE+tid];
        atomicAdd(&deg[et[tid]], 1.0f);
    }
    __syncthreads();
    if (tid < EE){
        int s = es[tid], t = et[tid];
        atomicAdd(&A[t*NN+s], rsqrtf(deg[s])*rsqrtf(deg[t]));
    }
    if (tid < NN){
        float r = rsqrtf(deg[tid]);
        atomicAdd(&A[tid*NN+tid], r*r);
    }
    __syncthreads();

    for (int idx = tid; idx < NN*NN; idx += blockDim.x){
        int n = idx / NN, m = idx % NN;
        float s = 0.0f;
        #pragma unroll
        for (int j = 0; j < NN; j++) s += A[n*NN+j]*A[j*NN+m];
        g_A2[idx] = s;
    }
    if (tid < NN){
        float s = 0.0f;
        #pragma unroll
        for (int m = 0; m < NN; m++) s += A[tid*NN+m];
        g_rA[tid] = s;
    }
    if (tid < CC){
        float s = 0.0f;
        for (int k = 0; k < CC; k++) s += b1[k]*W2[k*CC+tid];
        g_b1w2[tid] = s;
    }
}

// ---------------------------------------------------------------------------
// Main persistent kernel: 512 threads = TWO independent 256-thread halves,
// each running the R6-winning per-tile structure on its own tile, sharing
// one 64KB W12 smem copy.  16 warps/SM (4/SMSP) for latency hiding; crossbar
// at 192 wf-cyc vs 256 FFMA2-cyc per k (same 75% slack as R6).
//   stage 1: V[125,128] = X @ W12, 8x8 FFMA2 blocking, stride-129 X.
//   stage 2: warps 0..4 of each half own one graph; n chunked 9/8/8 to fit
//            the 128-reg/thread cap (512 thr x 128 = full RF).
// 1 block/SM (~201KB smem).
// ---------------------------------------------------------------------------
__global__ __launch_bounds__(512, 1)
void gcn_k(const float* __restrict__ x,
           const float* __restrict__ b2g,
           float* __restrict__ out){
    extern __shared__ float sm[];
    float* ws  = sm;            // W12 [k][c], 128x128 (shared by both halves)
    float* XV  = ws + WS_F;     // two per-half buffers (X stride 129, V stride 132)
    float* A2s = XV + 2*XV_F;   // 625 used / 640 reserved
    float* rAs = A2s + A2_F;    // 32
    float* bws = rAs + 32;      // 128 (16B-aligned)
    float* b2s = bws + CC;      // 128 (16B-aligned)

    const int tid  = threadIdx.x;
    const int h    = tid >> 8;        // half 0/1
    const int t1   = tid & 255;
    const int tc   = t1 & 15;
    const int tr   = t1 >> 4;
    const int c0   = tc << 3;
    const int lane = tid & 31;
    const int wid1 = t1 >> 5;         // warp id within half, 0..7

    for (int i = tid; i < WS_F/4; i += 512)
        ((float4*)ws)[i] = ((const float4*)g_W12)[i];
    for (int i = tid; i < NN*NN; i += 512) A2s[i] = g_A2[i];
    if (tid < NN) rAs[tid] = g_rA[tid];
    if (tid < CC) bws[tid] = g_b1w2[tid];
    else if (tid < 2*CC) b2s[tid-CC] = b2g[tid-CC];
    __syncthreads();

    float* Xh = XV + h*XV_F;

    for (int pair = blockIdx.x; pair < NTILES/2; pair += gridDim.x){
        const int tile = pair*2 + h;      // NTILES even -> always valid

        // ---- stage X: 125x128 rows, stride-129 layout ----
        const float4* xp = (const float4*)(x + (size_t)tile*(MR*CC));
        for (int i = t1; i < (MR*CC)/4; i += 256){
            float4 v = xp[i];
            int row = i >> 5, cb = (i & 31) << 2;
            float* d = Xh + row*XSTR + cb;
            d[0]=v.x; d[1]=v.y; d[2]=v.z; d[3]=v.w;
        }
        __syncthreads();

        // ---- stage 1: V = X @ W12 (rows 120..127 of tr=15 tile junk; never stored)
        u64 acc[8][4];
        #pragma unroll
        for (int i = 0; i < 8; i++)
            #pragma unroll
            for (int q = 0; q < 4; q++) acc[i][q] = 0ull;

        #pragma unroll 4
        for (int k = 0; k < VV; k++){
            const float* wr = ws + (k << 7) + c0;
            ulonglong2 wa = *(const ulonglong2*)wr;
            ulonglong2 wb = *(const ulonglong2*)(wr + 4);
            float af[8];
            #pragma unroll
            for (int i = 0; i < 8; i++) af[i] = Xh[(tr*8 + i)*XSTR + k];
            #pragma unroll
            for (int i = 0; i < 8; i++){
                u64 a = pk2(af[i]);
                ffma2(acc[i][0], a, wa.x);
                ffma2(acc[i][1], a, wa.y);
                ffma2(acc[i][2], a, wb.x);
                ffma2(acc[i][3], a, wb.y);
            }
        }
        __syncthreads();   // X fully consumed -> reuse buffer as V (stride 132)

        #pragma unroll
        for (int i = 0; i < 8; i++){
            int row = tr*8 + i;
            if (row < MR){
                ulonglong2* vp = (ulonglong2*)(Xh + row*VSTR + c0);
                ulonglong2 t0; t0.x = acc[i][0]; t0.y = acc[i][1];
                ulonglong2 t1v; t1v.x = acc[i][2]; t1v.y = acc[i][3];
                vp[0] = t0; vp[1] = t1v;
            }
        }
        __syncthreads();

        // ---- stage 2: warps 0..4 of each half own one graph; n chunked 9/8/8
        if (wid1 < GPT){
            const int g  = tile*GPT + wid1;
            const int cb = lane << 2;            // 4 cols per lane
            float4 bw = *(const float4*)(bws + cb);
            float4 bb = *(const float4*)(b2s + cb);
            float* zp = out + (size_t)g*(NN*CC) + cb;
            float ls = 0.0f, lss = 0.0f;

            #pragma unroll
            for (int ch = 0; ch < 3; ch++){
                const int n0 = (ch == 0) ? 0 : 9 + (ch-1)*8;
                const int nc = (ch == 0) ? 9 : 8;
                u64 z[9][2];
                #pragma unroll
                for (int n = 0; n < 9; n++){ z[n][0] = 0ull; z[n][1] = 0ull; }

                #pragma unroll 5
                for (int m = 0; m < NN; m++){
                    ulonglong2 v = *(const ulonglong2*)(Xh + (wid1*NN + m)*VSTR + cb);
                    #pragma unroll
                    for (int n = 0; n < 9; n++){
                        if (n < nc){
                            u64 a = pk2(A2s[(n0+n)*NN + m]);
                            ffma2(z[n][0], a, v.x);
                            ffma2(z[n][1], a, v.y);
                        }
                    }
                }
                #pragma unroll
                for (int n = 0; n < 9; n++){
                    if (n < nc){
                        float r = rAs[n0 + n];
                        float o0,o1,o2,o3;
                        upk(z[n][0], o0, o1);
                        upk(z[n][1], o2, o3);
                        o0 = fmaf(r, bw.x, o0) + bb.x;
                        o1 = fmaf(r, bw.y, o1) + bb.y;
                        o2 = fmaf(r, bw.z, o2) + bb.z;
                        o3 = fmaf(r, bw.w, o3) + bb.w;
                        ls += o0 + o1 + o2 + o3;
                        lss = fmaf(o0,o0, fmaf(o1,o1, fmaf(o2,o2, fmaf(o3,o3, lss))));
                        *(float4*)(zp + (n0+n)*CC) = make_float4(o0,o1,o2,o3);
                    }
                }
            }
            #pragma unroll
            for (int s = 16; s; s >>= 1){
                ls  += __shfl_xor_sync(0xffffffffu, ls,  s);
                lss += __shfl_xor_sync(0xffffffffu, lss, s);
            }
            if (lane == 0){
                int t = g % TT;
                atomicAdd(&g_stats[t],      ls);
                atomicAdd(&g_stats[TT + t], lss);
            }
        }
        __syncthreads();   // V reads done before next pair's X staging
    }
}

// BN finalize (per-block redundant) + in-place BN + ReLU, 8 float4 per iter.
__global__ void bn_k(const float* __restrict__ gamma,
                     const float* __restrict__ beta,
                     float* __restrict__ out){
    __shared__ float sc[TT], sh[TT];
    for (int t = threadIdx.x; t < TT; t += blockDim.x){
        float mean = g_stats[t] / CNT;
        float var  = g_stats[TT + t] / CNT - mean*mean;
        float s    = rsqrtf(var + 1e-5f) * gamma[t];
        sc[t] = s;
        sh[t] = beta[t] - mean*s;
    }
    __syncthreads();

    const int total32 = (NB*TT*NN*CC)/32;   // 640,000 groups of 8 float4
    int stride = gridDim.x * blockDim.x;
    for (int i = blockIdx.x*blockDim.x + threadIdx.x; i < total32; i += stride){
        int t = (i / 100) % TT;             // 100 = N*C/32 groups per (b,t)
        float s = sc[t], h = sh[t];
        float4* p = (float4*)out + (size_t)i*8;
        float4 v[8];
        #pragma unroll
        for (int q = 0; q < 8; q++) v[q] = p[q];
        #pragma unroll
        for (int q = 0; q < 8; q++){
            v[q].x = fmaxf(fmaf(v[q].x, s, h), 0.0f);
            v[q].y = fmaxf(fmaf(v[q].y, s, h), 0.0f);
            v[q].z = fmaxf(fmaf(v[q].z, s, h), 0.0f);
            v[q].w = fmaxf(fmaf(v[q].w, s, h), 0.0f);
        }
        #pragma unroll
        for (int q = 0; q < 8; q++) p[q] = v[q];
    }
}

extern "C" void kernel_launch(void* const* d_in, const int* in_sizes, int n_in,
                              void* d_out, int out_size){
    const float* x  = (const float*)d_in[0];
    const int*   ei = (const int*)  d_in[1];
    const float* W1 = (const float*)d_in[2];
    const float* b1 = (const float*)d_in[3];
    const float* W2 = (const float*)d_in[4];
    const float* b2 = (const float*)d_in[5];
    const float* ga = (const float*)d_in[6];
    const float* be = (const float*)d_in[7];
    float* out = (float*)d_out;

    int nsm = 148;
    cudaDeviceGetAttribute(&nsm, cudaDevAttrMultiProcessorCount, 0);

    const int smemB = (WS_F + 2*XV_F + A2_F + 32 + 2*CC) * (int)sizeof(float);
    cudaFuncSetAttribute(gcn_k, cudaFuncAttributeMaxDynamicSharedMemorySize, smemB);

    prep_k<<<CC, 256>>>(ei, W1, W2, b1);
    gcn_k<<<nsm, 512, smemB>>>(x, b2, out);
    bn_k<<<nsm*8, 256>>>(ga, be, out);
}

// round 16
// speedup vs baseline: 1.0306x; 1.0306x over previous
#include <cuda_runtime.h>
#include <cstdint>

#define NB 64
#define TT 100
#define NN 25
#define VV 128
#define CC 128
#define EE 64
#define NG (NB*TT)
#define GPT 5                 // graphs per tile
#define MR (GPT*NN)           // 125 rows per tile
#define NTILES (NG/GPT)       // 1280
#define XSTR 129              // X-tile stride: conflict-free scalar broadcasts
#define VSTR 132              // V-tile stride: 16B-aligned rows for LDS.128
#define WS_F 16384            // W12
#define XS_F 16128            // 125*129 = 16125, padded
#define VS_F 16512            // 125*132 = 16500, padded
#define A2_F 640              // 625 padded -> downstream float4 alignment
#define CNT ((float)(NB*NN*CC))

__device__ float g_A2[NN*NN];
__device__ float g_rA[NN];
__device__ float g_b1w2[CC];
__device__ float g_W12[VV*CC];
__device__ float g_stats[2*TT];

typedef unsigned long long u64;

__device__ __forceinline__ u64 pk2(float v){
    u64 r; unsigned u = __float_as_uint(v);
    asm("mov.b64 %0, {%1, %1};" : "=l"(r) : "r"(u));
    return r;
}
__device__ __forceinline__ void ffma2(u64 &d, u64 a, u64 b){
    asm("fma.rn.f32x2 %0, %1, %2, %0;" : "+l"(d) : "l"(a), "l"(b));
}
__device__ __forceinline__ void upk(u64 v, float &lo, float &hi){
    unsigned a,b; asm("mov.b64 {%0, %1}, %2;" : "=r"(a), "=r"(b) : "l"(v));
    lo = __uint_as_float(a); hi = __uint_as_float(b);
}

// ---------------------------------------------------------------------------
// Parallel prep (256 thr): every block computes one W12 row; block 0 builds
// normalized adjacency via shared atomics, A2, rowsum, b1^T W2, and zeroes
// ALL stats (replay idempotence).  Edge dtype auto-detected.
// ---------------------------------------------------------------------------
__global__ void prep_k(const int* __restrict__ ei,
                       const float* __restrict__ W1,
                       const float* __restrict__ W2,
                       const float* __restrict__ b1){
    __shared__ float A[NN*NN];
    __shared__ float row[CC];
    __shared__ float deg[NN];
    __shared__ int   es[EE], et[EE];
    __shared__ int   flag;
    const int tid = threadIdx.x;
    const int bi  = blockIdx.x;

    if (tid < CC) row[tid] = W1[bi*CC + tid];
    __syncthreads();
    if (tid < CC){
        float s = 0.0f;
        #pragma unroll 8
        for (int j = 0; j < CC; j++) s += row[j]*W2[j*CC+tid];
        g_W12[bi*CC+tid] = s;
    }

    if (bi != 0) return;

    if (tid < 2*TT) g_stats[tid] = 0.0f;
    if (tid == 0)   flag = 1;
    if (tid < NN)   deg[tid] = 1.0f;            // self-loops
    for (int i = tid; i < NN*NN; i += blockDim.x) A[i] = 0.0f;
    __syncthreads();

    if (tid < EE){  // int64 layout = [v,0] pairs in first 128 words
        int a = ei[2*tid], b = ei[2*tid+1];
        if (b != 0 || (unsigned)a >= (unsigned)NN) atomicExch(&flag, 0);
    }
    __syncthreads();
    const bool is64 = (flag != 0);
    if (tid < EE){
        es[tid] = is64 ? ei[2*tid]        : ei[tid];
        et[tid] = is64 ? ei[2*(EE+tid)]   : ei[EE+tid];
        atomicAdd(&deg[et[tid]], 1.0f);
    }
    __syncthreads();
    if (tid < EE){
        int s = es[tid], t = et[tid];
        atomicAdd(&A[t*NN+s], rsqrtf(deg[s])*rsqrtf(deg[t]));
    }
    if (tid < NN){
        float r = rsqrtf(deg[tid]);
        atomicAdd(&A[tid*NN+tid], r*r);
    }
    __syncthreads();

    for (int idx = tid; idx < NN*NN; idx += blockDim.x){
        int n = idx / NN, m = idx % NN;
        float s = 0.0f;
        #pragma unroll
        for (int j = 0; j < NN; j++) s += A[n*NN+j]*A[j*NN+m];
        g_A2[idx] = s;
    }
    if (tid < NN){
        float s = 0.0f;
        #pragma unroll
        for (int m = 0; m < NN; m++) s += A[tid*NN+m];
        g_rA[tid] = s;
    }
    if (tid < CC){
        float s = 0.0f;
        for (int k = 0; k < CC; k++) s += b1[k]*W2[k*CC+tid];
        g_b1w2[tid] = s;
    }
}

// ---------------------------------------------------------------------------
// Main persistent kernel, 256 thr, 1 block/SM (~195KB smem).
// Separate X and V buffers enable warp specialization:
//   stage 1 (all 8 warps):  V = X @ W12, 8x8 FFMA2 blocking (R6-proven).
//   after ONE sync:  warps 0..4 run stage 2 (Z = A2@V + bias -> gmem, stats)
//                    warps 5..7 stage the NEXT tile's X (prefetch overlap).
// 2 barriers per tile instead of 3; X DRAM fetch hidden under stage 2.
// ---------------------------------------------------------------------------
__global__ __launch_bounds__(256, 1)
void gcn_k(const float* __restrict__ x,
           const float* __restrict__ b2g,
           float* __restrict__ out){
    extern __shared__ float sm[];
    float* ws  = sm;            // W12 [k][c], 128x128
    float* Xs  = ws  + WS_F;    // X tile, stride 129
    float* Vs  = Xs  + XS_F;    // V tile, stride 132
    float* A2s = Vs  + VS_F;    // 625 used / 640 reserved
    float* rAs = A2s + A2_F;    // 32
    float* bws = rAs + 32;      // 128 (16B-aligned)
    float* b2s = bws + CC;      // 128 (16B-aligned)

    const int tid  = threadIdx.x;
    const int tc   = tid & 15;
    const int tr   = tid >> 4;
    const int c0   = tc << 3;
    const int lane = tid & 31;
    const int wid  = tid >> 5;

    for (int i = tid; i < WS_F/4; i += 256)
        ((float4*)ws)[i] = ((const float4*)g_W12)[i];
    for (int i = tid; i < NN*NN; i += 256) A2s[i] = g_A2[i];
    if (tid < NN) rAs[tid] = g_rA[tid];
    if (tid < CC) bws[tid] = g_b1w2[tid];
    else if (tid < 2*CC) b2s[tid-CC] = b2g[tid-CC];
    __syncthreads();

    // prologue: stage first tile's X with all threads (grid <= NTILES always)
    {
        const float4* xp = (const float4*)(x + (size_t)blockIdx.x*(MR*CC));
        for (int i = tid; i < (MR*CC)/4; i += 256){
            float4 v = xp[i];
            float* d = Xs + (i >> 5)*XSTR + ((i & 31) << 2);
            d[0]=v.x; d[1]=v.y; d[2]=v.z; d[3]=v.w;
        }
    }
    __syncthreads();

    for (int tile = blockIdx.x; tile < NTILES; tile += gridDim.x){
        // ---- stage 1: V = X @ W12 (rows 120..127 of tr=15 tile junk; never stored)
        u64 acc[8][4];
        #pragma unroll
        for (int i = 0; i < 8; i++)
            #pragma unroll
            for (int q = 0; q < 4; q++) acc[i][q] = 0ull;

        #pragma unroll 4
        for (int k = 0; k < VV; k++){
            const float* wr = ws + (k << 7) + c0;
            ulonglong2 wa = *(const ulonglong2*)wr;
            ulonglong2 wb = *(const ulonglong2*)(wr + 4);
            float af[8];
            #pragma unroll
            for (int i = 0; i < 8; i++) af[i] = Xs[(tr*8 + i)*XSTR + k];
            #pragma unroll
            for (int i = 0; i < 8; i++){
                u64 a = pk2(af[i]);
                ffma2(acc[i][0], a, wa.x);
                ffma2(acc[i][1], a, wa.y);
                ffma2(acc[i][2], a, wb.x);
                ffma2(acc[i][3], a, wb.y);
            }
        }

        #pragma unroll
        for (int i = 0; i < 8; i++){
            int row = tr*8 + i;
            if (row < MR){
                ulonglong2* vp = (ulonglong2*)(Vs + row*VSTR + c0);
                ulonglong2 t0; t0.x = acc[i][0]; t0.y = acc[i][1];
                ulonglong2 t1; t1.x = acc[i][2]; t1.y = acc[i][3];
                vp[0] = t0; vp[1] = t1;
            }
        }
        __syncthreads();   // V ready; all X reads done

        if (wid < GPT){
            // ---- stage 2: warps 0..4 each own one graph ----
            const int g = tile*GPT + wid;
            u64 z[NN][2];
            #pragma unroll
            for (int n = 0; n < NN; n++){ z[n][0] = 0ull; z[n][1] = 0ull; }

            #pragma unroll 5
            for (int m = 0; m < NN; m++){
                ulonglong2 v = *(const ulonglong2*)(Vs + (wid*NN + m)*VSTR + (lane << 2));
                #pragma unroll
                for (int n = 0; n < NN; n++){
                    u64 a = pk2(A2s[n*NN + m]);
                    ffma2(z[n][0], a, v.x);
                    ffma2(z[n][1], a, v.y);
                }
            }

            float4 bw = *(const float4*)(bws + (lane << 2));
            float4 bb = *(const float4*)(b2s + (lane << 2));
            float* zp = out + (size_t)g*(NN*CC) + (lane << 2);
            float ls = 0.0f, lss = 0.0f;
            #pragma unroll
            for (int n = 0; n < NN; n++){
                float r = rAs[n];
                float o0,o1,o2,o3;
                upk(z[n][0], o0, o1);
                upk(z[n][1], o2, o3);
                o0 = fmaf(r, bw.x, o0) + bb.x;
                o1 = fmaf(r, bw.y, o1) + bb.y;
                o2 = fmaf(r, bw.z, o2) + bb.z;
                o3 = fmaf(r, bw.w, o3) + bb.w;
                ls += o0 + o1 + o2 + o3;
                lss = fmaf(o0,o0, fmaf(o1,o1, fmaf(o2,o2, fmaf(o3,o3, lss))));
                *(float4*)(zp + n*CC) = make_float4(o0,o1,o2,o3);
            }
            #pragma unroll
            for (int s = 16; s; s >>= 1){
                ls  += __shfl_xor_sync(0xffffffffu, ls,  s);
                lss += __shfl_xor_sync(0xffffffffu, lss, s);
            }
            if (lane == 0){
                int t = g % TT;
                atomicAdd(&g_stats[t],      ls);
                atomicAdd(&g_stats[TT + t], lss);
            }
        } else {
            // ---- warps 5..7: prefetch next tile's X into Xs ----
            int nt = tile + gridDim.x;
            if (nt < NTILES){
                const float4* xp = (const float4*)(x + (size_t)nt*(MR*CC));
                for (int i = tid - GPT*32; i < (MR*CC)/4; i += 96){
                    float4 v = xp[i];
                    float* d = Xs + (i >> 5)*XSTR + ((i & 31) << 2);
                    d[0]=v.x; d[1]=v.y; d[2]=v.z; d[3]=v.w;
                }
            }
        }
        __syncthreads();   // stage2 V-reads + X prefetch complete
    }
}

// BN finalize (per-block redundant) + in-place BN + ReLU, 8 float4 per iter.
__global__ void bn_k(const float* __restrict__ gamma,
                     const float* __restrict__ beta,
                     float* __restrict__ out){
    __shared__ float sc[TT], sh[TT];
    for (int t = threadIdx.x; t < TT; t += blockDim.x){
        float mean = g_stats[t] / CNT;
        float var  = g_stats[TT + t] / CNT - mean*mean;
        float s    = rsqrtf(var + 1e-5f) * gamma[t];
        sc[t] = s;
        sh[t] = beta[t] - mean*s;
    }
    __syncthreads();

    const int total32 = (NB*TT*NN*CC)/32;   // 640,000 groups of 8 float4
    int stride = gridDim.x * blockDim.x;
    for (int i = blockIdx.x*blockDim.x + threadIdx.x; i < total32; i += stride){
        int t = (i / 100) % TT;             // 100 = N*C/32 groups per (b,t)
        float s = sc[t], h = sh[t];
        float4* p = (float4*)out + (size_t)i*8;
        float4 v[8];
        #pragma unroll
        for (int q = 0; q < 8; q++) v[q] = p[q];
        #pragma unroll
        for (int q = 0; q < 8; q++){
            v[q].x = fmaxf(fmaf(v[q].x, s, h), 0.0f);
            v[q].y = fmaxf(fmaf(v[q].y, s, h), 0.0f);
            v[q].z = fmaxf(fmaf(v[q].z, s, h), 0.0f);
            v[q].w = fmaxf(fmaf(v[q].w, s, h), 0.0f);
        }
        #pragma unroll
        for (int q = 0; q < 8; q++) p[q] = v[q];
    }
}

extern "C" void kernel_launch(void* const* d_in, const int* in_sizes, int n_in,
                              void* d_out, int out_size){
    const float* x  = (const float*)d_in[0];
    const int*   ei = (const int*)  d_in[1];
    const float* W1 = (const float*)d_in[2];
    const float* b1 = (const float*)d_in[3];
    const float* W2 = (const float*)d_in[4];
    const float* b2 = (const float*)d_in[5];
    const float* ga = (const float*)d_in[6];
    const float* be = (const float*)d_in[7];
    float* out = (float*)d_out;

    int nsm = 148;
    cudaDeviceGetAttribute(&nsm, cudaDevAttrMultiProcessorCount, 0);

    const int smemB = (WS_F + XS_F + VS_F + A2_F + 32 + 2*CC) * (int)sizeof(float);
    cudaFuncSetAttribute(gcn_k, cudaFuncAttributeMaxDynamicSharedMemorySize, smemB);

    prep_k<<<CC, 256>>>(ei, W1, W2, b1);
    gcn_k<<<nsm, 256, smemB>>>(x, b2, out);
    bn_k<<<nsm*8, 256>>>(ga, be, out);
}